// round 14
// baseline (speedup 1.0000x reference)
#include <cuda_runtime.h>

#define BN_EPS 1e-5f

// Scratch (allocation-free rule: __device__ globals)
__device__ __align__(16) float g_yT[8 * 64 * 64 * 64];   // (b, hy, w, o)  TRANSPOSED
__device__ __align__(16) float g_res[8 * 128 * 128];     // (b, h, w)
__device__ __align__(16) float g_wt2[64 * 64];           // w2 transposed [c][o]

// ---------------- f32x2 packed-FMA helpers (Blackwell dual-rate fp32) -------
typedef unsigned long long u64;

__device__ __forceinline__ u64 pack2(float lo, float hi) {
    u64 r;
    asm("mov.b64 %0, {%1, %2};" : "=l"(r) : "f"(lo), "f"(hi));
    return r;
}
__device__ __forceinline__ void unpack2(u64 v, float& lo, float& hi) {
    asm("mov.b64 {%0, %1}, %2;" : "=f"(lo), "=f"(hi) : "l"(v));
}
__device__ __forceinline__ void fma2(u64& d, u64 a, u64 b) {
    asm("fma.rn.f32x2 %0, %1, %2, %0;" : "+l"(d) : "l"(a), "l"(b));
}

__device__ __forceinline__ void cp_async16(void* smem_dst, const void* gptr) {
    unsigned sa = (unsigned)__cvta_generic_to_shared(smem_dst);
    asm volatile("cp.async.cg.shared.global [%0], [%1], 16;" :: "r"(sa), "l"(gptr));
}
__device__ __forceinline__ void cp_commit() {
    asm volatile("cp.async.commit_group;");
}
template <int N>
__device__ __forceinline__ void cp_wait() {
    asm volatile("cp.async.wait_group %0;" :: "n"(N));
}

// ---- Kernel A: res mean + conv1 + w2 transpose, one grid -------------------
__global__ void __launch_bounds__(256) prep_conv1_kernel(
    const float4* __restrict__ ref4, const float* __restrict__ x,
    const float* __restrict__ w1, const float* __restrict__ w2,
    const float* __restrict__ b1, const float* __restrict__ g1,
    const float* __restrict__ bt1, const float* __restrict__ m1,
    const float* __restrict__ v1)
{
#if __CUDA_ARCH__ >= 900
    cudaTriggerProgrammaticLaunchCompletion();   // let fuse's pre-sync part launch
#endif
    __shared__ __align__(16) float s_x[64 * 64];     // [c][w]
    __shared__ __align__(16) float s_wt[64 * 66];    // [c][o] padded; reused as stage
    __shared__ float s_A[64], s_B[64];

    int bid = blockIdx.x, t = threadIdx.x;

    if (bid < 512) {
        // ---- res path: high-MLP strided reduction ----
        int idx = bid * 256 + t;          // 4 threads per float4-pixel
        int quad = idx >> 2, q = idx & 3;
        int b = quad >> 12, p = quad & 4095;
        const float4* src = ref4 + (size_t)b * 262144 + (size_t)q * 16 * 4096 + p;
        float sx = 0.f, sy = 0.f, sz = 0.f, sw = 0.f;
#pragma unroll
        for (int c = 0; c < 16; c++) {
            float4 v = src[(size_t)c * 4096];
            sx += v.x; sy += v.y; sz += v.z; sw += v.w;
        }
#pragma unroll
        for (int m = 1; m <= 2; m <<= 1) {
            sx += __shfl_xor_sync(0xFFFFFFFFu, sx, m);
            sy += __shfl_xor_sync(0xFFFFFFFFu, sy, m);
            sz += __shfl_xor_sync(0xFFFFFFFFu, sz, m);
            sw += __shfl_xor_sync(0xFFFFFFFFu, sw, m);
        }
        if (q == 0) {
            const float f = 1.0f / 64.0f;
            ((float4*)g_res)[quad] = make_float4(sx * f, sy * f, sz * f, sw * f);
        }
        return;
    }
    if (bid >= 1024) {
        // ---- w2 transpose path ----
        int e0 = (bid - 1024) * 1024 + t;
#pragma unroll
        for (int k = 0; k < 4; k++) {
            int e = e0 + k * 256;
            int o = e >> 6, c = e & 63;
            g_wt2[c * 64 + o] = w2[e];
        }
        return;
    }

    // ---- conv1 path ----
    int blk = bid - 512;
    int h = blk & 63, b = blk >> 6;

    if (t < 64) {
        float sc = g1[t] * rsqrtf(v1[t] + BN_EPS);
        s_A[t] = sc;
        s_B[t] = b1[t] * sc + bt1[t] - m1[t] * sc;
    }
    const float* xrow = x + (size_t)b * 64 * 4096 + (size_t)h * 64;
    for (int i = t; i < 1024; i += 256) {
        int c = i >> 4, w4 = (i & 15) * 4;
        *(float4*)&s_x[c * 64 + w4] = *(const float4*)&xrow[(size_t)c * 4096 + w4];
    }
    for (int i = t; i < 4096; i += 256) {
        int o = i >> 6, c = i & 63;
        s_wt[c * 66 + o] = w1[i];
    }
    __syncthreads();

    int wg = t & 31, og = t >> 5;
    int w0 = wg * 2, o0 = og * 8;

    u64 acc[4][2];
#pragma unroll
    for (int i = 0; i < 4; i++)
#pragma unroll
        for (int j = 0; j < 2; j++) acc[i][j] = 0ull;

#pragma unroll 8
    for (int c = 0; c < 64; c++) {
        float2 rv = *(const float2*)&s_x[c * 64 + w0];
        u64 r0 = pack2(rv.x, rv.x);
        u64 r1 = pack2(rv.y, rv.y);
        const u64* wp = (const u64*)&s_wt[c * 66 + o0];
        u64 wv0 = wp[0], wv1 = wp[1], wv2 = wp[2], wv3 = wp[3];
        fma2(acc[0][0], wv0, r0); fma2(acc[0][1], wv0, r1);
        fma2(acc[1][0], wv1, r0); fma2(acc[1][1], wv1, r1);
        fma2(acc[2][0], wv2, r0); fma2(acc[2][1], wv2, r1);
        fma2(acc[3][0], wv3, r0); fma2(acc[3][1], wv3, r1);
    }
    __syncthreads();              // all mainloop smem reads done

    // stage [w][o] into s_wt (stride 66) using float2 (8B-aligned: idx even)
    float* s_stage = s_wt;
#pragma unroll
    for (int j = 0; j < 2; j++) {
        int wrow = (w0 + j) * 66;
#pragma unroll
        for (int i = 0; i < 4; i++) {
            int oA = o0 + 2 * i, oB = oA + 1;
            float lo, hi;
            unpack2(acc[i][j], lo, hi);
            float vA = fmaxf(lo * s_A[oA] + s_B[oA], 0.f);
            float vB = fmaxf(hi * s_A[oB] + s_B[oB], 0.f);
            *(float2*)&s_stage[wrow + oA] = make_float2(vA, vB);
        }
    }
    __syncthreads();

    // coalesced STG: g_yT[b][h][w][o] via float2
    float* ytbase = g_yT + ((size_t)(b * 64 + h)) * 4096;
    for (int i = t; i < 2048; i += 256) {
        int w = i >> 5, o2 = (i & 31) * 2;
        *(float2*)&ytbase[w * 64 + o2] = *(const float2*)&s_stage[w * 66 + o2];
    }
}

// ---------------- Kernel B: fused mask + aggregate + conv2 ------------------
// 256 threads/block; block handles TWO h-rows (h0 = 2*bx, h1 = h0+1).
// Thread tile = 8 o x 4 w x 2 rows. 2 blocks/SM.
// cp.async groups: G0=chunk0, G1=chunk1 (pre-grid-sync) | G2=wt, G3=yT | G4,G5=chunks 2,3
#define YT_STRIDE 72
#define YT_ROW    (64 * YT_STRIDE)          // 4608
#define SM_WT     8192
#define SM_YT     (SM_WT + 4096)            // 12288
#define SM_RES    (SM_YT + 3 * YT_ROW)      // 26112
#define SM_A      (SM_RES + 528)
#define SM_B      (SM_A + 64)
#define SM_MASK   (SM_B + 64)               // 2 x 128 float4 = 1024 floats
#define FUSE_SMEM_FLOATS (SM_MASK + 1024)
#define FUSE_SMEM_BYTES  (FUSE_SMEM_FLOATS * 4)

__global__ void __launch_bounds__(256, 2) fuse_kernel(
    const float* __restrict__ ref,
    const float* __restrict__ b2,  const float* __restrict__ g2,
    const float* __restrict__ bt2, const float* __restrict__ m2,
    const float* __restrict__ v2,  float* __restrict__ out)
{
    extern __shared__ float sm[];
    float* s_wt  = sm + SM_WT;
    float* s_yT  = sm + SM_YT;
    float* s_res = sm + SM_RES;
    float* s_A   = sm + SM_A;
    float* s_B   = sm + SM_B;
    float4* s_mask = (float4*)(sm + SM_MASK);

    int h0 = blockIdx.x * 2, b = blockIdx.y;
    int t = threadIdx.x;

    const float* rrow0 = ref + (size_t)b * 64 * 16384 + (size_t)h0 * 128;

    // chunk k: 16 channels x 128 w for BOTH rows -> ping buffer (k&1)
    auto issue = [&](int k) {
        float* buf = sm + (k & 1) * 4096;
#pragma unroll
        for (int r = 0; r < 2; r++) {
            int i = t + r * 256;                      // 512 float4 per row
            int cl = i >> 5, w4 = (i & 31) << 2;
            const float* src = rrow0 + (size_t)(k * 16 + cl) * 16384 + w4;
            cp_async16(buf + cl * 128 + w4,        src);          // row h0
            cp_async16(buf + 2048 + cl * 128 + w4, src + 128);    // row h1
        }
        cp_commit();
    };

    // --- pre-sync phase: ref traffic only (independent of prep) ---
    issue(0);                                         // G0
    issue(1);                                         // G1

#if __CUDA_ARCH__ >= 900
    cudaGridDependencySynchronize();                  // wait for prep's outputs
#endif

    // G2: transposed w2 (contiguous)
#pragma unroll
    for (int r = 0; r < 4; r++) {
        int i = t + r * 256;
        cp_async16(s_wt + i * 4, g_wt2 + i * 4);
    }
    cp_commit();

    // G3: three yT rows R-1, R, R+1 (clamped), R = h0/2
    int R = h0 >> 1;
    int yr[3];
    yr[0] = (R - 1 < 0) ? 0 : R - 1;
    yr[1] = R;
    yr[2] = (R + 1 > 63) ? 63 : R + 1;
    {
#pragma unroll
        for (int s = 0; s < 3; s++) {
            const float* src = g_yT + ((size_t)(b * 64 + yr[s])) * 4096;
#pragma unroll
            for (int r = 0; r < 4; r++) {
                int i = t + r * 256;                  // 1024 float4 per row
                int w = i >> 4, oc = (i & 15) * 4;
                cp_async16(&s_yT[s * YT_ROW + w * YT_STRIDE + oc], src + i * 4);
            }
        }
        cp_commit();
    }

    if (t < 64) {
        float sc = g2[t] * rsqrtf(v2[t] + BN_EPS);
        s_A[t] = sc;
        s_B[t] = b2[t] * sc + bt2[t] - m2[t] * sc;
    }
    // res rows h0-1 .. h0+2 (4 rows), zero padded cols
    for (int i = t; i < 4 * 132; i += 256) {
        int j = i / 132, col = i % 132;
        int rr = h0 - 1 + j, wc = col - 1;
        float v = 0.f;
        if (col < 130 && rr >= 0 && rr < 128 && wc >= 0 && wc < 128)
            v = g_res[((size_t)b * 128 + rr) * 128 + wc];
        s_res[i] = v;
    }

    // lane mapping: og = l>>2 (8), wq = l&3 (4)
    int wid = t >> 5, l = t & 31;
    int og = l >> 2, wq = l & 3;
    int w0 = wid * 16 + wq * 4;          // 4 w per thread (x128 total)
    int o0 = og * 8;                     // 8 o per thread

    u64 acc[2][4][4];                    // [row][o-pair][w]
#pragma unroll
    for (int r = 0; r < 2; r++)
#pragma unroll
        for (int i = 0; i < 4; i++)
#pragma unroll
            for (int j = 0; j < 4; j++) acc[r][i][j] = 0ull;

#pragma unroll
    for (int k = 0; k < 4; k++) {
        if (k == 0)      cp_wait<1>();   // G0,G1,G2 done (chunk0 + wt)
        else if (k == 1) cp_wait<2>();   // chunk1 already retired
        else if (k == 2) cp_wait<1>();   // G3(yT) + G4(chunk2) done
        else             cp_wait<0>();   // G5(chunk3) done
        __syncthreads();
        const float* bufp = sm + (k & 1) * 4096;
#pragma unroll
        for (int cl = 0; cl < 16; cl++) {
            int c = k * 16 + cl;
            const u64* wp = (const u64*)&s_wt[c * 64 + o0];
            u64 wv0 = wp[0], wv1 = wp[1], wv2 = wp[2], wv3 = wp[3];
#pragma unroll
            for (int r = 0; r < 2; r++) {
                float4 rv = *(const float4*)&bufp[r * 2048 + cl * 128 + w0];
                u64 rr0 = pack2(rv.x, rv.x);
                u64 rr1 = pack2(rv.y, rv.y);
                u64 rr2 = pack2(rv.z, rv.z);
                u64 rr3 = pack2(rv.w, rv.w);
                fma2(acc[r][0][0], wv0, rr0); fma2(acc[r][0][1], wv0, rr1);
                fma2(acc[r][0][2], wv0, rr2); fma2(acc[r][0][3], wv0, rr3);
                fma2(acc[r][1][0], wv1, rr0); fma2(acc[r][1][1], wv1, rr1);
                fma2(acc[r][1][2], wv1, rr2); fma2(acc[r][1][3], wv1, rr3);
                fma2(acc[r][2][0], wv2, rr0); fma2(acc[r][2][1], wv2, rr1);
                fma2(acc[r][2][2], wv2, rr2); fma2(acc[r][2][3], wv2, rr3);
                fma2(acc[r][3][0], wv3, rr0); fma2(acc[r][3][1], wv3, rr1);
                fma2(acc[r][3][2], wv3, rr2); fma2(acc[r][3][3], wv3, rr3);
            }
        }
        if (k + 2 < 4) {
            __syncthreads();
            issue(k + 2);                             // G4, G5
        }
    }

    // ---- mask weights: ONE thread per (row, w) -> smem float4 table --------
    {
        int r = t >> 7, w = t & 127;                  // 2 x 128 = 256 threads
        int h = h0 + r;
        const int rs0 = 1 - r;
        const float* resb = s_res + r * 132;
        float ur[9];
        float sum9 = 0.f;
#pragma unroll
        for (int di = 0; di < 3; di++)
#pragma unroll
            for (int dj = 0; dj < 3; dj++) {
                float v = resb[di * 132 + w + dj];
                ur[di * 3 + dj] = v;
                sum9 += v;
            }
        float ua = sum9 * (1.f / 9.f);
        bool ui = (ur[4] - ua) > 0.f;
        float W[2][2] = {{0.f, 0.f}, {0.f, 0.f}};
        float den = 1e-6f;
        int cs0 = 1 - (w & 1);
#pragma unroll
        for (int di = 0; di < 3; di++) {
            int hh = h + di - 1;
            bool rvalid = (hh >= 0) && (hh < 128);
            int rsel = (di == 0) ? 0 : ((di == 2) ? 1 : rs0);
#pragma unroll
            for (int dj = 0; dj < 3; dj++) {
                int ww = w + dj - 1;
                bool cvalid = (ww >= 0) && (ww < 128);
                bool up = (ur[di * 3 + dj] - ua) > 0.f;
                float mk = (up == ui) ? 1.f : 0.f;
                den += mk;
                int csel = (dj == 0) ? 0 : ((dj == 2) ? 1 : cs0);
                if (rvalid && cvalid) W[rsel][csel] += mk;
            }
        }
        float rd = 1.0f / den;
        s_mask[r * 128 + w] = make_float4(W[0][0] * rd, W[0][1] * rd,
                                          W[1][0] * rd, W[1][1] * rd);
    }
    __syncthreads();

    // y column indices for this thread's 4 w (shared by both rows)
    int Q = w0 >> 2;
    int cols[4];
    cols[0] = (2 * Q - 1 < 0) ? 0 : 2 * Q - 1;
    cols[1] = 2 * Q;
    cols[2] = 2 * Q + 1;
    cols[3] = (2 * Q + 2 > 63) ? 63 : 2 * Q + 2;
    const int c0i[4] = {0, 1, 1, 2};
    const int c1i[4] = {1, 2, 2, 3};

    // ---- per-row epilogue: aggregate + conv2 BN/ReLU -----------------------
#pragma unroll
    for (int r = 0; r < 2; r++) {
        int h = h0 + r;
        const float* ys0 = s_yT + (r + 0) * YT_ROW;   // slots (0,1) or (1,2)
        const float* ys1 = s_yT + (r + 1) * YT_ROW;

        float4 mk[4];
#pragma unroll
        for (int j = 0; j < 4; j++) mk[j] = s_mask[r * 128 + w0 + j];

        float* outrow = out + (size_t)b * 64 * 16384 + (size_t)h * 128;
#pragma unroll
        for (int p = 0; p < 4; p++) {
            int ob = o0 + 2 * p;
            float2 yv0[4], yv1[4];
#pragma unroll
            for (int cc = 0; cc < 4; cc++) {
                yv0[cc] = *(const float2*)&ys0[cols[cc] * YT_STRIDE + ob];
                yv1[cc] = *(const float2*)&ys1[cols[cc] * YT_STRIDE + ob];
            }
            int oA = ob, oB = ob + 1;
            float AA = s_A[oA], BA = s_B[oA];
            float AB = s_A[oB], BB = s_B[oB];
            float rlo[4], rhi[4];
#pragma unroll
            for (int j = 0; j < 4; j++) {
                float lo, hi;
                unpack2(acc[r][p][j], lo, hi);
                float convA = fmaxf(lo * AA + BA, 0.f);
                float convB = fmaxf(hi * AB + BB, 0.f);
                float2 a0 = yv0[c0i[j]], a1 = yv0[c1i[j]];
                float2 b0 = yv1[c0i[j]], b1 = yv1[c1i[j]];
                rlo[j] = mk[j].x * a0.x + mk[j].y * a1.x
                       + mk[j].z * b0.x + mk[j].w * b1.x + convA;
                rhi[j] = mk[j].x * a0.y + mk[j].y * a1.y
                       + mk[j].z * b0.y + mk[j].w * b1.y + convB;
            }
            *(float4*)&outrow[(size_t)oA * 16384 + w0] =
                make_float4(rlo[0], rlo[1], rlo[2], rlo[3]);
            *(float4*)&outrow[(size_t)oB * 16384 + w0] =
                make_float4(rhi[0], rhi[1], rhi[2], rhi[3]);
        }
    }
}

// ---------------------------------------------------------------------------
extern "C" void kernel_launch(void* const* d_in, const int* in_sizes, int n_in,
                              void* d_out, int out_size) {
    (void)in_sizes; (void)n_in; (void)out_size;
    const float* x   = (const float*)d_in[0];
    const float* ref = (const float*)d_in[1];
    const float* w1  = (const float*)d_in[2];
    const float* b1  = (const float*)d_in[3];
    const float* g1  = (const float*)d_in[4];
    const float* bt1 = (const float*)d_in[5];
    const float* m1  = (const float*)d_in[6];
    const float* v1  = (const float*)d_in[7];
    const float* w2  = (const float*)d_in[8];
    const float* b2  = (const float*)d_in[9];
    const float* g2  = (const float*)d_in[10];
    const float* bt2 = (const float*)d_in[11];
    const float* m2  = (const float*)d_in[12];
    const float* v2  = (const float*)d_in[13];
    float* out = (float*)d_out;

    cudaFuncSetAttribute(fuse_kernel, cudaFuncAttributeMaxDynamicSharedMemorySize,
                         FUSE_SMEM_BYTES);

    prep_conv1_kernel<<<1028, 256>>>((const float4*)ref, x, w1, w2,
                                     b1, g1, bt1, m1, v1);

    // fuse with programmatic dependent launch: pre-sync phase streams ref
    cudaLaunchConfig_t cfg = {};
    cfg.gridDim = dim3(64, 8);
    cfg.blockDim = dim3(256);
    cfg.dynamicSmemBytes = FUSE_SMEM_BYTES;
    cfg.stream = 0;
    cudaLaunchAttribute at[1];
    at[0].id = cudaLaunchAttributeProgrammaticStreamSerialization;
    at[0].val.programmaticStreamSerializationAllowed = 1;
    cfg.attrs = at;
    cfg.numAttrs = 1;
    cudaError_t err = cudaLaunchKernelEx(&cfg, fuse_kernel,
                                         ref, b2, g2, bt2, m2, v2, out);
    if (err != cudaSuccess) {
        // fallback: plain launch (no PDL)
        fuse_kernel<<<dim3(64, 8), 256, FUSE_SMEM_BYTES>>>(ref, b2, g2, bt2,
                                                           m2, v2, out);
    }
}

// round 15
// speedup vs baseline: 1.0078x; 1.0078x over previous
#include <cuda_runtime.h>

#define BN_EPS 1e-5f

// Scratch (allocation-free rule: __device__ globals)
__device__ __align__(16) float g_yT[8 * 64 * 64 * 64];   // (b, hy, w, o)  TRANSPOSED
__device__ __align__(16) float g_res[8 * 128 * 128];     // (b, h, w)
__device__ __align__(16) float g_wt2[64 * 64];           // w2 transposed [c][o]

// ---------------- f32x2 packed-FMA helpers (Blackwell dual-rate fp32) -------
typedef unsigned long long u64;

__device__ __forceinline__ u64 pack2(float lo, float hi) {
    u64 r;
    asm("mov.b64 %0, {%1, %2};" : "=l"(r) : "f"(lo), "f"(hi));
    return r;
}
__device__ __forceinline__ void unpack2(u64 v, float& lo, float& hi) {
    asm("mov.b64 {%0, %1}, %2;" : "=f"(lo), "=f"(hi) : "l"(v));
}
__device__ __forceinline__ void fma2(u64& d, u64 a, u64 b) {
    asm("fma.rn.f32x2 %0, %1, %2, %0;" : "+l"(d) : "l"(a), "l"(b));
}

__device__ __forceinline__ void cp_async16(void* smem_dst, const void* gptr) {
    unsigned sa = (unsigned)__cvta_generic_to_shared(smem_dst);
    asm volatile("cp.async.cg.shared.global [%0], [%1], 16;"
                 :: "r"(sa), "l"(gptr) : "memory");
}
__device__ __forceinline__ void cp_commit() {
    asm volatile("cp.async.commit_group;" ::: "memory");
}
template <int N>
__device__ __forceinline__ void cp_wait() {
    asm volatile("cp.async.wait_group %0;" :: "n"(N) : "memory");
}

// ---- Kernel A: res mean + conv1 + w2 transpose, one grid -------------------
__global__ void __launch_bounds__(256) prep_conv1_kernel(
    const float4* __restrict__ ref4, const float* __restrict__ x,
    const float* __restrict__ w1, const float* __restrict__ w2,
    const float* __restrict__ b1, const float* __restrict__ g1,
    const float* __restrict__ bt1, const float* __restrict__ m1,
    const float* __restrict__ v1)
{
    __shared__ __align__(16) float s_x[64 * 64];     // [c][w]
    __shared__ __align__(16) float s_wt[64 * 66];    // [c][o] padded; reused as stage
    __shared__ float s_A[64], s_B[64];

    int bid = blockIdx.x, t = threadIdx.x;

    if (bid < 512) {
        // ---- res path: high-MLP strided reduction ----
        int idx = bid * 256 + t;          // 4 threads per float4-pixel
        int quad = idx >> 2, q = idx & 3;
        int b = quad >> 12, p = quad & 4095;
        const float4* src = ref4 + (size_t)b * 262144 + (size_t)q * 16 * 4096 + p;
        float sx = 0.f, sy = 0.f, sz = 0.f, sw = 0.f;
#pragma unroll
        for (int c = 0; c < 16; c++) {
            float4 v = src[(size_t)c * 4096];
            sx += v.x; sy += v.y; sz += v.z; sw += v.w;
        }
#pragma unroll
        for (int m = 1; m <= 2; m <<= 1) {
            sx += __shfl_xor_sync(0xFFFFFFFFu, sx, m);
            sy += __shfl_xor_sync(0xFFFFFFFFu, sy, m);
            sz += __shfl_xor_sync(0xFFFFFFFFu, sz, m);
            sw += __shfl_xor_sync(0xFFFFFFFFu, sw, m);
        }
        if (q == 0) {
            const float f = 1.0f / 64.0f;
            ((float4*)g_res)[quad] = make_float4(sx * f, sy * f, sz * f, sw * f);
        }
        return;
    }
    if (bid >= 1024) {
        // ---- w2 transpose path ----
        int e0 = (bid - 1024) * 1024 + t;
#pragma unroll
        for (int k = 0; k < 4; k++) {
            int e = e0 + k * 256;
            int o = e >> 6, c = e & 63;
            g_wt2[c * 64 + o] = w2[e];
        }
        return;
    }

    // ---- conv1 path ----
    int blk = bid - 512;
    int h = blk & 63, b = blk >> 6;

    if (t < 64) {
        float sc = g1[t] * rsqrtf(v1[t] + BN_EPS);
        s_A[t] = sc;
        s_B[t] = b1[t] * sc + bt1[t] - m1[t] * sc;
    }
    const float* xrow = x + (size_t)b * 64 * 4096 + (size_t)h * 64;
    for (int i = t; i < 1024; i += 256) {
        int c = i >> 4, w4 = (i & 15) * 4;
        *(float4*)&s_x[c * 64 + w4] = *(const float4*)&xrow[(size_t)c * 4096 + w4];
    }
    for (int i = t; i < 4096; i += 256) {
        int o = i >> 6, c = i & 63;
        s_wt[c * 66 + o] = w1[i];
    }
    __syncthreads();

    int wg = t & 31, og = t >> 5;
    int w0 = wg * 2, o0 = og * 8;

    u64 acc[4][2];
#pragma unroll
    for (int i = 0; i < 4; i++)
#pragma unroll
        for (int j = 0; j < 2; j++) acc[i][j] = 0ull;

#pragma unroll 8
    for (int c = 0; c < 64; c++) {
        float2 rv = *(const float2*)&s_x[c * 64 + w0];
        u64 r0 = pack2(rv.x, rv.x);
        u64 r1 = pack2(rv.y, rv.y);
        const u64* wp = (const u64*)&s_wt[c * 66 + o0];
        u64 wv0 = wp[0], wv1 = wp[1], wv2 = wp[2], wv3 = wp[3];
        fma2(acc[0][0], wv0, r0); fma2(acc[0][1], wv0, r1);
        fma2(acc[1][0], wv1, r0); fma2(acc[1][1], wv1, r1);
        fma2(acc[2][0], wv2, r0); fma2(acc[2][1], wv2, r1);
        fma2(acc[3][0], wv3, r0); fma2(acc[3][1], wv3, r1);
    }
    __syncthreads();              // all mainloop smem reads done

    // stage [w][o] into s_wt (stride 66) using float2 (8B-aligned: idx even)
    float* s_stage = s_wt;
#pragma unroll
    for (int j = 0; j < 2; j++) {
        int wrow = (w0 + j) * 66;
#pragma unroll
        for (int i = 0; i < 4; i++) {
            int oA = o0 + 2 * i, oB = oA + 1;
            float lo, hi;
            unpack2(acc[i][j], lo, hi);
            float vA = fmaxf(lo * s_A[oA] + s_B[oA], 0.f);
            float vB = fmaxf(hi * s_A[oB] + s_B[oB], 0.f);
            *(float2*)&s_stage[wrow + oA] = make_float2(vA, vB);
        }
    }
    __syncthreads();

    // coalesced STG: g_yT[b][h][w][o] via float2
    float* ytbase = g_yT + ((size_t)(b * 64 + h)) * 4096;
    for (int i = t; i < 2048; i += 256) {
        int w = i >> 5, o2 = (i & 31) * 2;
        *(float2*)&ytbase[w * 64 + o2] = *(const float2*)&s_stage[w * 66 + o2];
    }
}

// ---------------- Kernel B: fused mask + aggregate + conv2 ------------------
// 256 threads/block; block handles TWO h-rows (h0 = 2*bx, h1 = h0+1).
// Thread tile = 8 o x 4 w x 2 rows. 2 blocks/SM. BARRIER-FREE mainloop:
// each warp cp.asyncs its OWN 16-w slice of the ref chunks; per-thread
// wait_group makes chunk waits warp-local.
// Per-thread cp group order: G0=chunk0(own) G1=wt(coop) G2=chunk1(own)
// G3=yT(coop) G4=chunk2(own) G5=chunk3(own)
#define YT_STRIDE 72
#define YT_ROW    (64 * YT_STRIDE)          // 4608
#define SM_WT     8192
#define SM_YT     (SM_WT + 4096)            // 12288
#define SM_RES    (SM_YT + 3 * YT_ROW)      // 26112
#define SM_A      (SM_RES + 528)
#define SM_B      (SM_A + 64)
#define SM_MASK   (SM_B + 64)               // 2 x 128 float4 = 1024 floats
#define FUSE_SMEM_FLOATS (SM_MASK + 1024)
#define FUSE_SMEM_BYTES  (FUSE_SMEM_FLOATS * 4)

__global__ void __launch_bounds__(256, 2) fuse_kernel(
    const float* __restrict__ ref,
    const float* __restrict__ b2,  const float* __restrict__ g2,
    const float* __restrict__ bt2, const float* __restrict__ m2,
    const float* __restrict__ v2,  float* __restrict__ out)
{
    extern __shared__ float sm[];
    float* s_wt  = sm + SM_WT;
    float* s_yT  = sm + SM_YT;
    float* s_res = sm + SM_RES;
    float* s_A   = sm + SM_A;
    float* s_B   = sm + SM_B;
    float4* s_mask = (float4*)(sm + SM_MASK);

    int h0 = blockIdx.x * 2, b = blockIdx.y;
    int t = threadIdx.x;
    int wid = t >> 5, l = t & 31;

    const float* rrow0 = ref + (size_t)b * 64 * 16384 + (size_t)h0 * 128;

    // per-warp: issue THIS warp's 16-w slice of chunk k (16 ch x 2 rows)
    auto issue_own = [&](int k) {
        float* buf = sm + (k & 1) * 4096;
        int wbase = wid * 16;
#pragma unroll
        for (int j = 0; j < 4; j++) {
            int i = l + 32 * j;              // 0..127
            int q4 = (i & 3) * 4;            // 16B quarter within 64B slice
            int r = (i >> 2) & 1;
            int cl = i >> 3;                 // 0..15
            const float* src = rrow0 + (size_t)(k * 16 + cl) * 16384
                             + r * 128 + wbase + q4;
            cp_async16(buf + r * 2048 + cl * 128 + wbase + q4, src);
        }
        cp_commit();
    };

    issue_own(0);                                     // G0

    // G1: transposed w2 (cooperative, contiguous)
#pragma unroll
    for (int r = 0; r < 4; r++) {
        int i = t + r * 256;
        cp_async16(s_wt + i * 4, g_wt2 + i * 4);
    }
    cp_commit();

    issue_own(1);                                     // G2

    // G3: three yT rows R-1, R, R+1 (clamped), R = h0/2 (cooperative)
    int R = h0 >> 1;
    int yr[3];
    yr[0] = (R - 1 < 0) ? 0 : R - 1;
    yr[1] = R;
    yr[2] = (R + 1 > 63) ? 63 : R + 1;
    {
#pragma unroll
        for (int s = 0; s < 3; s++) {
            const float* src = g_yT + ((size_t)(b * 64 + yr[s])) * 4096;
#pragma unroll
            for (int r = 0; r < 4; r++) {
                int i = t + r * 256;                  // 1024 float4 per row
                int w = i >> 4, oc = (i & 15) * 4;
                cp_async16(&s_yT[s * YT_ROW + w * YT_STRIDE + oc], src + i * 4);
            }
        }
        cp_commit();
    }

    if (t < 64) {
        float sc = g2[t] * rsqrtf(v2[t] + BN_EPS);
        s_A[t] = sc;
        s_B[t] = b2[t] * sc + bt2[t] - m2[t] * sc;
    }
    // res rows h0-1 .. h0+2 (4 rows), zero padded cols
    for (int i = t; i < 4 * 132; i += 256) {
        int j = i / 132, col = i % 132;
        int rr = h0 - 1 + j, wc = col - 1;
        float v = 0.f;
        if (col < 130 && rr >= 0 && rr < 128 && wc >= 0 && wc < 128)
            v = g_res[((size_t)b * 128 + rr) * 128 + wc];
        s_res[i] = v;
    }

    // lane mapping: og = l>>2 (8), wq = l&3 (4)
    int og = l >> 2, wq = l & 3;
    int w0 = wid * 16 + wq * 4;          // 4 w per thread (x128 total)
    int o0 = og * 8;                     // 8 o per thread

    u64 acc[2][4][4];                    // [row][o-pair][w]
#pragma unroll
    for (int r = 0; r < 2; r++)
#pragma unroll
        for (int i = 0; i < 4; i++)
#pragma unroll
            for (int j = 0; j < 4; j++) acc[r][i][j] = 0ull;

    // wait chunk0(own) + wt(coop); ONE barrier makes wt visible to all.
    cp_wait<2>();
    __syncthreads();

    // ---- BARRIER-FREE mainloop: warp-local waits only ----
#pragma unroll
    for (int k = 0; k < 4; k++) {
        if (k == 1)      cp_wait<2>();   // G2 (own chunk1) done
        else if (k == 2) cp_wait<1>();   // G3+G4 done (own chunk2)
        else if (k == 3) cp_wait<0>();   // G5 (own chunk3) done
        const float* bufp = sm + (k & 1) * 4096;
#pragma unroll
        for (int cl = 0; cl < 16; cl++) {
            int c = k * 16 + cl;
            const u64* wp = (const u64*)&s_wt[c * 64 + o0];
            u64 wv0 = wp[0], wv1 = wp[1], wv2 = wp[2], wv3 = wp[3];
#pragma unroll
            for (int r = 0; r < 2; r++) {
                float4 rv = *(const float4*)&bufp[r * 2048 + cl * 128 + w0];
                u64 rr0 = pack2(rv.x, rv.x);
                u64 rr1 = pack2(rv.y, rv.y);
                u64 rr2 = pack2(rv.z, rv.z);
                u64 rr3 = pack2(rv.w, rv.w);
                fma2(acc[r][0][0], wv0, rr0); fma2(acc[r][0][1], wv0, rr1);
                fma2(acc[r][0][2], wv0, rr2); fma2(acc[r][0][3], wv0, rr3);
                fma2(acc[r][1][0], wv1, rr0); fma2(acc[r][1][1], wv1, rr1);
                fma2(acc[r][1][2], wv1, rr2); fma2(acc[r][1][3], wv1, rr3);
                fma2(acc[r][2][0], wv2, rr0); fma2(acc[r][2][1], wv2, rr1);
                fma2(acc[r][2][2], wv2, rr2); fma2(acc[r][2][3], wv2, rr3);
                fma2(acc[r][3][0], wv3, rr0); fma2(acc[r][3][1], wv3, rr1);
                fma2(acc[r][3][2], wv3, rr2); fma2(acc[r][3][3], wv3, rr3);
            }
        }
        if (k + 2 < 4) issue_own(k + 2);              // G4, G5 (warp-local)
    }

    __syncthreads();   // yT (G3, coop) + res now visible to all

    // ---- mask weights: ONE thread per (row, w) -> smem float4 table --------
    {
        int r = t >> 7, w = t & 127;                  // 2 x 128 = 256 threads
        int h = h0 + r;
        const int rs0 = 1 - r;
        const float* resb = s_res + r * 132;
        float ur[9];
        float sum9 = 0.f;
#pragma unroll
        for (int di = 0; di < 3; di++)
#pragma unroll
            for (int dj = 0; dj < 3; dj++) {
                float v = resb[di * 132 + w + dj];
                ur[di * 3 + dj] = v;
                sum9 += v;
            }
        float ua = sum9 * (1.f / 9.f);
        bool ui = (ur[4] - ua) > 0.f;
        float W[2][2] = {{0.f, 0.f}, {0.f, 0.f}};
        float den = 1e-6f;
        int cs0 = 1 - (w & 1);
#pragma unroll
        for (int di = 0; di < 3; di++) {
            int hh = h + di - 1;
            bool rvalid = (hh >= 0) && (hh < 128);
            int rsel = (di == 0) ? 0 : ((di == 2) ? 1 : rs0);
#pragma unroll
            for (int dj = 0; dj < 3; dj++) {
                int ww = w + dj - 1;
                bool cvalid = (ww >= 0) && (ww < 128);
                bool up = (ur[di * 3 + dj] - ua) > 0.f;
                float mk = (up == ui) ? 1.f : 0.f;
                den += mk;
                int csel = (dj == 0) ? 0 : ((dj == 2) ? 1 : cs0);
                if (rvalid && cvalid) W[rsel][csel] += mk;
            }
        }
        float rd = 1.0f / den;
        s_mask[r * 128 + w] = make_float4(W[0][0] * rd, W[0][1] * rd,
                                          W[1][0] * rd, W[1][1] * rd);
    }
    __syncthreads();

    // y column indices for this thread's 4 w (shared by both rows)
    int Q = w0 >> 2;
    int cols[4];
    cols[0] = (2 * Q - 1 < 0) ? 0 : 2 * Q - 1;
    cols[1] = 2 * Q;
    cols[2] = 2 * Q + 1;
    cols[3] = (2 * Q + 2 > 63) ? 63 : 2 * Q + 2;
    const int c0i[4] = {0, 1, 1, 2};
    const int c1i[4] = {1, 2, 2, 3};

    // ---- per-row epilogue: aggregate + conv2 BN/ReLU -----------------------
#pragma unroll
    for (int r = 0; r < 2; r++) {
        int h = h0 + r;
        const float* ys0 = s_yT + (r + 0) * YT_ROW;   // slots (0,1) or (1,2)
        const float* ys1 = s_yT + (r + 1) * YT_ROW;

        float4 mk[4];
#pragma unroll
        for (int j = 0; j < 4; j++) mk[j] = s_mask[r * 128 + w0 + j];

        float* outrow = out + (size_t)b * 64 * 16384 + (size_t)h * 128;
#pragma unroll
        for (int p = 0; p < 4; p++) {
            int ob = o0 + 2 * p;
            float2 yv0[4], yv1[4];
#pragma unroll
            for (int cc = 0; cc < 4; cc++) {
                yv0[cc] = *(const float2*)&ys0[cols[cc] * YT_STRIDE + ob];
                yv1[cc] = *(const float2*)&ys1[cols[cc] * YT_STRIDE + ob];
            }
            int oA = ob, oB = ob + 1;
            float AA = s_A[oA], BA = s_B[oA];
            float AB = s_A[oB], BB = s_B[oB];
            float rlo[4], rhi[4];
#pragma unroll
            for (int j = 0; j < 4; j++) {
                float lo, hi;
                unpack2(acc[r][p][j], lo, hi);
                float convA = fmaxf(lo * AA + BA, 0.f);
                float convB = fmaxf(hi * AB + BB, 0.f);
                float2 a0 = yv0[c0i[j]], a1 = yv0[c1i[j]];
                float2 b0 = yv1[c0i[j]], b1 = yv1[c1i[j]];
                rlo[j] = mk[j].x * a0.x + mk[j].y * a1.x
                       + mk[j].z * b0.x + mk[j].w * b1.x + convA;
                rhi[j] = mk[j].x * a0.y + mk[j].y * a1.y
                       + mk[j].z * b0.y + mk[j].w * b1.y + convB;
            }
            *(float4*)&outrow[(size_t)oA * 16384 + w0] =
                make_float4(rlo[0], rlo[1], rlo[2], rlo[3]);
            *(float4*)&outrow[(size_t)oB * 16384 + w0] =
                make_float4(rhi[0], rhi[1], rhi[2], rhi[3]);
        }
    }
}

// ---------------------------------------------------------------------------
extern "C" void kernel_launch(void* const* d_in, const int* in_sizes, int n_in,
                              void* d_out, int out_size) {
    (void)in_sizes; (void)n_in; (void)out_size;
    const float* x   = (const float*)d_in[0];
    const float* ref = (const float*)d_in[1];
    const float* w1  = (const float*)d_in[2];
    const float* b1  = (const float*)d_in[3];
    const float* g1  = (const float*)d_in[4];
    const float* bt1 = (const float*)d_in[5];
    const float* m1  = (const float*)d_in[6];
    const float* v1  = (const float*)d_in[7];
    const float* w2  = (const float*)d_in[8];
    const float* b2  = (const float*)d_in[9];
    const float* g2  = (const float*)d_in[10];
    const float* bt2 = (const float*)d_in[11];
    const float* m2  = (const float*)d_in[12];
    const float* v2  = (const float*)d_in[13];
    float* out = (float*)d_out;

    cudaFuncSetAttribute(fuse_kernel, cudaFuncAttributeMaxDynamicSharedMemorySize,
                         FUSE_SMEM_BYTES);

    prep_conv1_kernel<<<1028, 256>>>((const float4*)ref, x, w1, w2,
                                     b1, g1, bt1, m1, v1);
    fuse_kernel<<<dim3(64, 8), 256, FUSE_SMEM_BYTES>>>(ref, b2, g2, bt2,
                                                       m2, v2, out);
}